// round 10
// baseline (speedup 1.0000x reference)
#include <cuda_runtime.h>

#define EPSF 1e-7f
#define P_TOT 900
#define NCH 144
#define COUT 32

// Scratch (no allocations allowed)
static __device__ float g_zz[P_TOT * NCH * COUT];   // [p][n][c]
static __device__ float g_rr[P_TOT * NCH * COUT];   // [p][n][c]
static __device__ float g_W5[NCH * 4 * 2 * 32 * 2]; // [n][k][jp][c][j2]

// W[(n*32+c)*16 + k*4 + j] -> W5[(((n*4+k)*2 + j/2)*32 + c)*2 + (j&1)]
__global__ void __launch_bounds__(256) wtrans_kernel(const float* __restrict__ W) {
    int t = blockIdx.x * 256 + threadIdx.x;
    if (t < NCH * COUT * 16) {
        int j = t & 3, k = (t >> 2) & 3, c = (t >> 4) & 31, n = t >> 9;
        g_W5[(((n * 4 + k) * 2 + (j >> 1)) * 32 + c) * 2 + (j & 1)] = W[t];
    }
}

// CTA = 256 threads = 8 warps = ONE parent.
// warp w: wj = w&1 (j-pair half: j in {2wj, 2wj+1}), wh = w>>1 (children
// quarter: n in [36wh, 36wh+36)). lane = c. Each thread computes 8 vote
// elements (4 i x 2 j) per child; W loads are coalesced float2 (256B/warp).
// MODE 0: rr uniform, M+E.  MODE 1: read rr, M+E.  MODE 2: M only, outputs.
template<int MODE>
__global__ void __launch_bounds__(256, 3) me_kernel(
    const float* __restrict__ pose,
    const float* __restrict__ beta_a, const float* __restrict__ beta_v,
    float* __restrict__ out, float lambd)
{
    __shared__ float sA[NCH * 16];          // child poses
    __shared__ float sPart[8][2][256];      // [warp][s|q][e8*32+c]; aliased as sPE in E
    __shared__ float sRs[4][32];            // [wh][c] (from wj==0)
    __shared__ float sLK[2][2][32];         // [wj][l|K][c]

    const int t = threadIdx.x;
    const int lane = t & 31, w = t >> 5;
    const int wj = w & 1, wh = w >> 1;
    const int p = blockIdx.x;
    const int pr = p / 30, pcl = p % 30;

    // gather child poses (float4, 64B rows)
    for (int idx = t; idx < NCH * 4; idx += 256) {
        int n = idx >> 2, vq = idx & 3;
        int k = n >> 4, ci = n & 15;
        int q = (pr + k / 3) * 32 + pcl + (k % 3);
        float4 val = reinterpret_cast<const float4*>(pose + q * 256 + ci * 16)[vq];
        *reinterpret_cast<float4*>(&sA[n * 16 + vq * 4]) = val;
    }
    __syncthreads();

    const float2* W5b = reinterpret_cast<const float2*>(g_W5) + lane;  // +((n*4+k)*2+wj)*32
    const float* rrb = g_rr + (size_t)p * 4608 + lane;                 // + n*32
    const int n0 = wh * 36;
    const int c = lane;

    // ---- M step: software-pipelined over 36 children, 8 elements/thread ----
    float s[8], q[8];
#pragma unroll
    for (int e = 0; e < 8; e++) { s[e] = 0.f; q[e] = 0.f; }
    float rs = 0.f;

    float2 cw0, cw1, cw2, cw3;
    {
        const int b = (n0 * 4 * 2 + wj) * 32;
        cw0 = W5b[b]; cw1 = W5b[b + 64]; cw2 = W5b[b + 128]; cw3 = W5b[b + 192];
    }
    float crr = (MODE == 0) ? 0.f : __ldg(rrb + n0 * 32);

#pragma unroll 2
    for (int nn = 0; nn < 36; nn++) {
        const int n = n0 + nn;
        const int np = (n + 1 < 144) ? n + 1 : 143;
        const int bp = (np * 8 + wj) * 32;
        float2 nw0 = W5b[bp], nw1 = W5b[bp + 64], nw2 = W5b[bp + 128], nw3 = W5b[bp + 192];
        float nrr = (MODE == 0) ? 0.f : __ldg(rrb + np * 32);

        const float4* Ap = reinterpret_cast<const float4*>(sA + n * 16);
        if (MODE != 0) rs += crr;
#pragma unroll
        for (int i = 0; i < 4; i++) {
            float4 a = Ap[i];
            float v0 = a.x * cw0.x + a.y * cw1.x + a.z * cw2.x + a.w * cw3.x;
            float v1 = a.x * cw0.y + a.y * cw1.y + a.z * cw2.y + a.w * cw3.y;
            if (MODE == 0) {
                s[i*2+0] += v0; q[i*2+0] += v0 * v0;
                s[i*2+1] += v1; q[i*2+1] += v1 * v1;
            } else {
                s[i*2+0] += crr * v0; q[i*2+0] += crr * (v0 * v0);
                s[i*2+1] += crr * v1; q[i*2+1] += crr * (v1 * v1);
            }
        }
        cw0 = nw0; cw1 = nw1; cw2 = nw2; cw3 = nw3; crr = nrr;
    }

    // exchange partials (combine over the 4 children-quarters, per wj)
#pragma unroll
    for (int e = 0; e < 8; e++) {
        sPart[w][0][e * 32 + lane] = s[e];
        sPart[w][1][e * 32 + lane] = q[e];
    }
    if (MODE != 0 && wj == 0) sRs[wh][lane] = rs;
    __syncthreads();

    const float rs_t = (MODE == 0) ? 4.5f
                     : (sRs[0][lane] + sRs[1][lane] + sRs[2][lane] + sRs[3][lane]);
    const float inv  = (MODE == 0) ? (1.f / 144.f) : (1.f / rs_t);

    float mean[8], yv[8], t2[8];
    float l = 0.f, Kc = 0.f;
#pragma unroll
    for (int e = 0; e < 8; e++) {
        float se = sPart[wj][0][e * 32 + lane] + sPart[wj + 2][0][e * 32 + lane]
                 + sPart[wj + 4][0][e * 32 + lane] + sPart[wj + 6][0][e * 32 + lane];
        float qe = sPart[wj][1][e * 32 + lane] + sPart[wj + 2][1][e * 32 + lane]
                 + sPart[wj + 4][1][e * 32 + lane] + sPart[wj + 6][1][e * 32 + lane];
        float m = se * inv;
        mean[e] = m;
        float var = fmaxf(qe * inv - m * m, 1e-30f);
        l += __logf(sqrtf(var) + EPSF);
        float y = 0.5f / var;
        yv[e] = y;
        t2[e] = -2.f * m * y;
        Kc += m * m * y;
    }
    if (wh == 0) { sLK[wj][0][lane] = l; sLK[wj][1][lane] = Kc; }
    __syncthreads();
    const float l_full = sLK[0][0][lane] + sLK[1][0][lane];
    const float K_full = sLK[0][1][lane] + sLK[1][1][lane];

    const float cost = 16.f * beta_v[c] + rs_t * l_full;
    const float act = 1.f / (1.f + __expf(-lambd * (beta_a[c] - cost)));

    if (MODE == 2) {
        if (wh == 0) {
            if (wj == 0) out[p * COUT + c] = act;
            float* op = out + 28800 + (size_t)p * 512 + c * 16 + 2 * wj;
#pragma unroll
            for (int i = 0; i < 4; i++) {
                op[i * 4]     = mean[i * 2 + 0];
                op[i * 4 + 1] = mean[i * 2 + 1];
            }
        }
        return;
    }

    // ---- E step: chunks of 12 children; pe halves combined via smem ----
    const float zb2 = __logf(act + EPSF) - l_full - K_full;
    float* sPE = &sPart[0][0][0];          // alias: [wh*12+nn][c], 6KB used
    float* zzb = g_zz + (size_t)p * 4608;

    {
        const int b = (n0 * 8 + wj) * 32;
        cw0 = W5b[b]; cw1 = W5b[b + 64]; cw2 = W5b[b + 128]; cw3 = W5b[b + 192];
    }
#pragma unroll 1
    for (int ch = 0; ch < 3; ch++) {
        float peL[12];
#pragma unroll 2
        for (int nn = 0; nn < 12; nn++) {
            const int n = n0 + ch * 12 + nn;
            const int np = (n + 1 < 144) ? n + 1 : 143;
            const int bp = (np * 8 + wj) * 32;
            float2 nw0 = W5b[bp], nw1 = W5b[bp + 64], nw2 = W5b[bp + 128], nw3 = W5b[bp + 192];

            const float4* Ap = reinterpret_cast<const float4*>(sA + n * 16);
            float pe = 0.f;
#pragma unroll
            for (int i = 0; i < 4; i++) {
                float4 a = Ap[i];
                float v0 = a.x * cw0.x + a.y * cw1.x + a.z * cw2.x + a.w * cw3.x;
                float v1 = a.x * cw0.y + a.y * cw1.y + a.z * cw2.y + a.w * cw3.y;
                pe += v0 * fmaf(v0, yv[i*2+0], t2[i*2+0]);
                pe += v1 * fmaf(v1, yv[i*2+1], t2[i*2+1]);
            }
            peL[nn] = pe;
            cw0 = nw0; cw1 = nw1; cw2 = nw2; cw3 = nw3;
        }
        __syncthreads();                       // sPE region free for this chunk
        if (wj == 1) {
#pragma unroll
            for (int nn = 0; nn < 12; nn++)
                sPE[(wh * 12 + nn) * 32 + lane] = peL[nn];
        }
        __syncthreads();
        if (wj == 0) {
#pragma unroll
            for (int nn = 0; nn < 12; nn++) {
                const int n = n0 + ch * 12 + nn;
                zzb[n * 32 + lane] = zb2 - peL[nn] - sPE[(wh * 12 + nn) * 32 + lane];
            }
        }
    }
}

// Softmax over parent axis p for every (n,c) on layout [p][n][c].
// One block per n (144), 1024 threads = 32 c x 32 p-stripes.
__global__ void __launch_bounds__(1024) softmax_kernel()
{
    __shared__ float red[32 * 33];
    __shared__ float gv[32];
    const int n = blockIdx.x;
    const int t = threadIdx.x;
    const int c = t & 31, st = t >> 5;
    const int base = n * 32 + c;

    float m = -1e30f;
    for (int p = st; p < P_TOT; p += 32)
        m = fmaxf(m, g_zz[(size_t)p * 4608 + base]);
    red[st * 33 + c] = m;
    __syncthreads();
    if (t < 32) {
        float M = red[t];
#pragma unroll
        for (int i = 1; i < 32; i++) M = fmaxf(M, red[i * 33 + t]);
        gv[t] = M;
    }
    __syncthreads();
    const float M = gv[c];

    float s = 0.f;
    for (int p = st; p < P_TOT; p += 32)
        s += __expf(g_zz[(size_t)p * 4608 + base] - M);
    red[st * 33 + c] = s;
    __syncthreads();
    if (t < 32) {
        float S = 0.f;
#pragma unroll
        for (int i = 0; i < 32; i++) S += red[i * 33 + t];
        gv[t] = 1.f / S;
    }
    __syncthreads();
    const float Sinv = gv[c];

    for (int p = st; p < P_TOT; p += 32) {
        size_t idx = (size_t)p * 4608 + base;
        g_rr[idx] = __expf(g_zz[idx] - M) * Sinv;
    }
}

extern "C" void kernel_launch(void* const* d_in, const int* in_sizes, int n_in,
                              void* d_out, int out_size)
{
    const float* pose = (const float*)d_in[1];
    const float* W    = (const float*)d_in[2];
    const float* ba   = (const float*)d_in[3];
    const float* bv   = (const float*)d_in[4];
    float* out = (float*)d_out;

    wtrans_kernel<<<288, 256>>>(W);
    me_kernel<0><<<P_TOT, 256>>>(pose, ba, bv, out, 0.0f);
    softmax_kernel<<<NCH, 1024>>>();
    me_kernel<1><<<P_TOT, 256>>>(pose, ba, bv, out, 0.0005f);
    softmax_kernel<<<NCH, 1024>>>();
    me_kernel<2><<<P_TOT, 256>>>(pose, ba, bv, out, 0.000975f);
}

// round 11
// speedup vs baseline: 1.1961x; 1.1961x over previous
#include <cuda_runtime.h>

#define EPSF 1e-7f
#define P_TOT 900
#define NCH 144
#define COUT 32
#define L2E 1.4426950408889634f

// Scratch (no allocations allowed)
static __device__ float g_zz[P_TOT * NCH * COUT];   // [p][n][c], log2-scaled
static __device__ float g_C2[NCH * COUT];           // per-(n,c) softmax log2-normalizer
static __device__ float g_W4[NCH * COUT * 16];      // [n][k][c][j] coalesced

__device__ __forceinline__ float ex2(float x) {
    float r; asm("ex2.approx.f32 %0,%1;" : "=f"(r) : "f"(x)); return r;
}
__device__ __forceinline__ float lg2(float x) {
    float r; asm("lg2.approx.f32 %0,%1;" : "=f"(r) : "f"(x)); return r;
}

// W[(n*32+c)*16 + k*4 + j] -> W4[((n*4+k)*32 + c)*4 + j]
__global__ void __launch_bounds__(256) wtrans_kernel(const float* __restrict__ W) {
    int t = blockIdx.x * 256 + threadIdx.x;   // over 144*32*4 float4 rows
    if (t < NCH * COUT * 4) {
        int k = t & 3, c = (t >> 2) & 31, n = t >> 7;
        float4 v = reinterpret_cast<const float4*>(W)[t];
        reinterpret_cast<float4*>(g_W4)[(n * 4 + k) * 32 + c] = v;
    }
}

// CTA = 128 threads = 4 warps = ONE parent; warp w handles children
// n in [36w, 36w+36). lane = c. Per n each warp issues 4 fully coalesced
// LDG.128 (512B contiguous) from W4.
// rr is never materialized: rr = ex2(zz2 - C2) computed on the MUFU pipe.
// MODE 0: rr uniform (unweighted sums), M+E.
// MODE 1: rr on the fly, M+E.   MODE 2: rr on the fly, M only, outputs.
template<int MODE>
__global__ void __launch_bounds__(128, 4) me_kernel(
    const float* __restrict__ pose,
    const float* __restrict__ beta_a, const float* __restrict__ beta_v,
    float* __restrict__ out, float lambd)
{
    __shared__ float sA[NCH * 16];            // child poses
    __shared__ float sPart[4][2][512];        // [warp][s/q][e*32+c]
    __shared__ float sRs[4][32];              // [warp][c]

    const int t = threadIdx.x;
    const int lane = t & 31, w = t >> 5;
    const int p = blockIdx.x;
    const int pr = p / 30, pcl = p % 30;

    // gather child poses (float4, 64B rows)
    for (int idx = t; idx < NCH * 4; idx += 128) {
        int n = idx >> 2, vq = idx & 3;
        int k = n >> 4, ci = n & 15;
        int q = (pr + k / 3) * 32 + pcl + (k % 3);
        float4 val = reinterpret_cast<const float4*>(pose + q * 256 + ci * 16)[vq];
        *reinterpret_cast<float4*>(&sA[n * 16 + vq * 4]) = val;
    }
    __syncthreads();

    const int c = lane;
    const float4* W4 = reinterpret_cast<const float4*>(g_W4) + c;   // + n*128 + k*32
    const float* zzr = g_zz + (size_t)p * 4608 + lane;              // + n*32
    const float* c2r = g_C2 + lane;                                 // + n*32
    const int n0 = w * 36;

    // ---- M step: software-pipelined over 36 children ----
    float s[16], q[16];
#pragma unroll
    for (int e = 0; e < 16; e++) { s[e] = 0.f; q[e] = 0.f; }
    float rs = 0.f;

    float4 cw0, cw1, cw2, cw3;
    {
        const float4* q4 = W4 + n0 * 128;
        cw0 = q4[0]; cw1 = q4[32]; cw2 = q4[64]; cw3 = q4[96];
    }
    float carg = (MODE == 0) ? 0.f
               : (__ldg(zzr + n0 * 32) - __ldg(c2r + n0 * 32));

#pragma unroll 2
    for (int nn = 0; nn < 36; nn++) {
        const int n = n0 + nn;
        const int np = (n + 1 < 144) ? n + 1 : 143;
        const float4* q4n = W4 + np * 128;
        float4 nw0 = q4n[0], nw1 = q4n[32], nw2 = q4n[64], nw3 = q4n[96];
        float narg = (MODE == 0) ? 0.f
                   : (__ldg(zzr + np * 32) - __ldg(c2r + np * 32));

        const float4* Ap = reinterpret_cast<const float4*>(sA + n * 16);
        float crr;
        if (MODE != 0) { crr = ex2(carg); rs += crr; }
#pragma unroll
        for (int i = 0; i < 4; i++) {
            float4 a = Ap[i];
            float vx = a.x * cw0.x + a.y * cw1.x + a.z * cw2.x + a.w * cw3.x;
            float vy = a.x * cw0.y + a.y * cw1.y + a.z * cw2.y + a.w * cw3.y;
            float vz = a.x * cw0.z + a.y * cw1.z + a.z * cw2.z + a.w * cw3.z;
            float vw = a.x * cw0.w + a.y * cw1.w + a.z * cw2.w + a.w * cw3.w;
            if (MODE == 0) {
                s[i*4+0] += vx; q[i*4+0] += vx * vx;
                s[i*4+1] += vy; q[i*4+1] += vy * vy;
                s[i*4+2] += vz; q[i*4+2] += vz * vz;
                s[i*4+3] += vw; q[i*4+3] += vw * vw;
            } else {
                s[i*4+0] += crr * vx; q[i*4+0] += crr * (vx * vx);
                s[i*4+1] += crr * vy; q[i*4+1] += crr * (vy * vy);
                s[i*4+2] += crr * vz; q[i*4+2] += crr * (vz * vz);
                s[i*4+3] += crr * vw; q[i*4+3] += crr * (vw * vw);
            }
        }
        cw0 = nw0; cw1 = nw1; cw2 = nw2; cw3 = nw3; carg = narg;
    }

    // exchange partials among the 4 warps
#pragma unroll
    for (int e = 0; e < 16; e++) {
        sPart[w][0][e * 32 + lane] = s[e];
        sPart[w][1][e * 32 + lane] = q[e];
    }
    if (MODE != 0) sRs[w][lane] = rs;
    __syncthreads();

    const float rs_t = (MODE == 0) ? 4.5f
                     : (sRs[0][lane] + sRs[1][lane] + sRs[2][lane] + sRs[3][lane]);
    const float inv  = (MODE == 0) ? (1.f / 144.f) : (1.f / rs_t);

    float mean[16], i2v[16], t2[16];
    float l = 0.f, Kc = 0.f;
#pragma unroll
    for (int e = 0; e < 16; e++) {
        float se = sPart[0][0][e * 32 + lane] + sPart[1][0][e * 32 + lane]
                 + sPart[2][0][e * 32 + lane] + sPart[3][0][e * 32 + lane];
        float qe = sPart[0][1][e * 32 + lane] + sPart[1][1][e * 32 + lane]
                 + sPart[2][1][e * 32 + lane] + sPart[3][1][e * 32 + lane];
        float m = se * inv;
        mean[e] = m;
        float var = fmaxf(qe * inv - m * m, 1e-30f);
        l += __logf(sqrtf(var) + EPSF);
        float y = 0.5f / var;
        i2v[e] = y * L2E;             // pre-scaled to log2 domain (E only)
        t2[e] = -2.f * m * y * L2E;
        Kc += m * m * y;
    }
    const float cost = 16.f * beta_v[c] + rs_t * l;
    const float act = 1.f / (1.f + __expf(-lambd * (beta_a[c] - cost)));

    if (MODE == 2) {
        if (w == 0) {
            out[p * COUT + c] = act;
            float4* op = reinterpret_cast<float4*>(out + 28800 + (size_t)p * 512 + c * 16);
#pragma unroll
            for (int i = 0; i < 4; i++) {
                float4 m4 = { mean[i*4+0], mean[i*4+1], mean[i*4+2], mean[i*4+3] };
                op[i] = m4;
            }
        }
        return;
    }

    // ---- E step: recompute votes (pipelined); zz2 = (zb - pe) in log2 units
    const float zb2 = (__logf(act + EPSF) - l - Kc) * L2E;
    float* zzb = g_zz + (size_t)p * 4608 + c;

    {
        const float4* q4 = W4 + n0 * 128;
        cw0 = q4[0]; cw1 = q4[32]; cw2 = q4[64]; cw3 = q4[96];
    }
#pragma unroll 2
    for (int nn = 0; nn < 36; nn++) {
        const int n = n0 + nn;
        const int np = (n + 1 < 144) ? n + 1 : 143;
        const float4* q4n = W4 + np * 128;
        float4 nw0 = q4n[0], nw1 = q4n[32], nw2 = q4n[64], nw3 = q4n[96];

        const float4* Ap = reinterpret_cast<const float4*>(sA + n * 16);
        float pe = 0.f;
#pragma unroll
        for (int i = 0; i < 4; i++) {
            float4 a = Ap[i];
            float vx = a.x * cw0.x + a.y * cw1.x + a.z * cw2.x + a.w * cw3.x;
            float vy = a.x * cw0.y + a.y * cw1.y + a.z * cw2.y + a.w * cw3.y;
            float vz = a.x * cw0.z + a.y * cw1.z + a.z * cw2.z + a.w * cw3.z;
            float vw = a.x * cw0.w + a.y * cw1.w + a.z * cw2.w + a.w * cw3.w;
            pe += vx * fmaf(vx, i2v[i*4+0], t2[i*4+0]);
            pe += vy * fmaf(vy, i2v[i*4+1], t2[i*4+1]);
            pe += vz * fmaf(vz, i2v[i*4+2], t2[i*4+2]);
            pe += vw * fmaf(vw, i2v[i*4+3], t2[i*4+3]);
        }
        zzb[n * 32] = zb2 - pe;
        cw0 = nw0; cw1 = nw1; cw2 = nw2; cw3 = nw3;
    }
}

// Softmax normalizer over parent axis p for every (n,c) on layout [p][n][c].
// Writes only C2[n][c] = max2 + log2(sum exp2(zz2 - max2)).
// One block per n (144), 1024 threads = 32 c x 32 p-stripes.
__global__ void __launch_bounds__(1024) colog_kernel()
{
    __shared__ float red[32 * 33];
    __shared__ float gv[32];
    const int n = blockIdx.x;
    const int t = threadIdx.x;
    const int c = t & 31, st = t >> 5;
    const int base = n * 32 + c;

    float m = -1e30f;
    for (int p = st; p < P_TOT; p += 32)
        m = fmaxf(m, g_zz[(size_t)p * 4608 + base]);
    red[st * 33 + c] = m;
    __syncthreads();
    if (t < 32) {
        float M = red[t];
#pragma unroll
        for (int i = 1; i < 32; i++) M = fmaxf(M, red[i * 33 + t]);
        gv[t] = M;
    }
    __syncthreads();
    const float M = gv[c];

    float s = 0.f;
    for (int p = st; p < P_TOT; p += 32)
        s += ex2(g_zz[(size_t)p * 4608 + base] - M);
    red[st * 33 + c] = s;
    __syncthreads();
    if (t < 32) {
        float S = 0.f;
#pragma unroll
        for (int i = 0; i < 32; i++) S += red[i * 33 + t];
        g_C2[n * 32 + t] = gv[t] + lg2(S);
    }
}

extern "C" void kernel_launch(void* const* d_in, const int* in_sizes, int n_in,
                              void* d_out, int out_size)
{
    const float* pose = (const float*)d_in[1];
    const float* W    = (const float*)d_in[2];
    const float* ba   = (const float*)d_in[3];
    const float* bv   = (const float*)d_in[4];
    float* out = (float*)d_out;

    wtrans_kernel<<<72, 256>>>(W);
    me_kernel<0><<<P_TOT, 128>>>(pose, ba, bv, out, 0.0f);
    colog_kernel<<<NCH, 1024>>>();
    me_kernel<1><<<P_TOT, 128>>>(pose, ba, bv, out, 0.0005f);
    colog_kernel<<<NCH, 1024>>>();
    me_kernel<2><<<P_TOT, 128>>>(pose, ba, bv, out, 0.000975f);
}